// round 16
// baseline (speedup 1.0000x reference)
#include <cuda_runtime.h>
#include <cuda_fp16.h>
#include <cstdint>

// ---------------------------------------------------------------------------
// Problem constants
// ---------------------------------------------------------------------------
#define BB 8
#define TT 1024
#define CC 1024
#define HH 16
#define DD 64
#define NTOK (BB * TT)           // 8192
#define SCALE_ATTN 0.07216878364870323f  // 1/sqrt(3*C/H) = 1/sqrt(192)

// ---------------------------------------------------------------------------
// Scratch (device globals) — fp16 activations
// ---------------------------------------------------------------------------
__device__ __half g_h[NTOK * CC];          // ln1 out
__device__ __half g_qkv[NTOK * 3 * CC];    // qkv
__device__ __half g_y[NTOK * CC];          // attn out
__device__ __half g_h2[NTOK * CC];         // ln2 out
__device__ __half g_mid[NTOK * 4 * CC];    // mlp hidden
// transposed fp16 weights, [N][K] row-major
#define OFF_QKV  0
#define OFF_PROJ (3 * CC * CC)
#define OFF_W1   (OFF_PROJ + CC * CC)
#define OFF_W2   (OFF_W1 + 4 * CC * CC)
#define WP_TOTAL (OFF_W2 + 4 * CC * CC)
__device__ __half g_wt[WP_TOTAL];

// ---------------------------------------------------------------------------
// Helpers
// ---------------------------------------------------------------------------
__device__ __forceinline__ void mma_f16(float* c, const uint32_t* a, const uint32_t* b) {
    asm volatile(
        "mma.sync.aligned.m16n8k16.row.col.f32.f16.f16.f32 "
        "{%0,%1,%2,%3}, {%4,%5,%6,%7}, {%8,%9}, {%0,%1,%2,%3};"
        : "+f"(c[0]), "+f"(c[1]), "+f"(c[2]), "+f"(c[3])
        : "r"(a[0]), "r"(a[1]), "r"(a[2]), "r"(a[3]), "r"(b[0]), "r"(b[1]));
}

// streaming copy: L2-only (.cg) — tile data is never re-read through L1
__device__ __forceinline__ void cp_async16(void* smem_ptr, const void* gptr) {
    uint32_t sp = (uint32_t)__cvta_generic_to_shared(smem_ptr);
    asm volatile("cp.async.cg.shared.global [%0], [%1], 16;" :: "r"(sp), "l"(gptr));
}

__device__ __forceinline__ uint32_t smem_u32(const void* p) {
    return (uint32_t)__cvta_generic_to_shared(p);
}

__device__ __forceinline__ void ldsm4(uint32_t* r, uint32_t a) {
    asm volatile("ldmatrix.sync.aligned.m8n8.x4.shared.b16 {%0,%1,%2,%3}, [%4];"
        : "=r"(r[0]), "=r"(r[1]), "=r"(r[2]), "=r"(r[3]) : "r"(a));
}
__device__ __forceinline__ void ldsm4t(uint32_t* r, uint32_t a) {
    asm volatile("ldmatrix.sync.aligned.m8n8.x4.trans.shared.b16 {%0,%1,%2,%3}, [%4];"
        : "=r"(r[0]), "=r"(r[1]), "=r"(r[2]), "=r"(r[3]) : "r"(a));
}

__device__ __forceinline__ uint32_t h2bits(float a, float b) {
    __half2 h = __floats2half2_rn(a, b);
    return *reinterpret_cast<uint32_t*>(&h);
}

// ---------------------------------------------------------------------------
// Weight transpose + fp16 round: W[K][N] fp32 -> Wt[N][K] fp16
// ---------------------------------------------------------------------------
__global__ __launch_bounds__(256)
void transpose_w(const float* __restrict__ W, __half* __restrict__ Wt, int K, int N) {
    __shared__ float t[32][33];
    const int n0 = blockIdx.x * 32;
    const int k0 = blockIdx.y * 32;
    const int tx = threadIdx.x, ty = threadIdx.y;
    #pragma unroll
    for (int i = 0; i < 4; i++)
        t[ty + 8 * i][tx] = W[(size_t)(k0 + ty + 8 * i) * N + n0 + tx];
    __syncthreads();
    #pragma unroll
    for (int i = 0; i < 4; i++)
        Wt[(size_t)(n0 + ty + 8 * i) * K + k0 + tx] = __float2half_rn(t[tx][ty + 8 * i]);
}

// ---------------------------------------------------------------------------
// LayerNorm: one block per row; fp32 in -> fp16 out
// ---------------------------------------------------------------------------
__global__ __launch_bounds__(256)
void ln_kernel(const float* __restrict__ x, const float* __restrict__ g,
               const float* __restrict__ b, __half* __restrict__ out) {
    __shared__ float rs[8];
    __shared__ float rq[8];
    const int row = blockIdx.x;
    const float* xr = x + (size_t)row * CC;
    __half* yr = out + (size_t)row * CC;
    const int c = threadIdx.x * 4;

    float4 v = *(const float4*)(xr + c);
    float s  = v.x + v.y + v.z + v.w;
    float sq = v.x * v.x + v.y * v.y + v.z * v.z + v.w * v.w;
    #pragma unroll
    for (int o = 16; o; o >>= 1) {
        s  += __shfl_xor_sync(0xffffffffu, s, o);
        sq += __shfl_xor_sync(0xffffffffu, sq, o);
    }
    if ((threadIdx.x & 31) == 0) { rs[threadIdx.x >> 5] = s; rq[threadIdx.x >> 5] = sq; }
    __syncthreads();
    s = 0.f; sq = 0.f;
    #pragma unroll
    for (int i = 0; i < 8; i++) { s += rs[i]; sq += rq[i]; }

    const float mean = s * (1.f / CC);
    const float var  = sq * (1.f / CC) - mean * mean;
    const float rstd = rsqrtf(var + 1e-5f);

    float4 g4 = *(const float4*)(g + c);
    float4 b4 = *(const float4*)(b + c);
    *(__half2*)(yr + c)     = __floats2half2_rn((v.x - mean) * rstd * g4.x + b4.x,
                                                (v.y - mean) * rstd * g4.y + b4.y);
    *(__half2*)(yr + c + 2) = __floats2half2_rn((v.z - mean) * rstd * g4.z + b4.z,
                                                (v.w - mean) * rstd * g4.w + b4.w);
}

// ---------------------------------------------------------------------------
// FP16 tensor GEMM: C[M,N] = A[M,K] @ Wt[N,K]^T + bias (+Res | relu)
// CTA tile 256x128, BK=64, 3-stage cp.async, one sync per k-iter,
// 8 warps (4m x 2n), warp tile 64x64, register double-buffered ldmatrix feed.
// Mainloop order: frags(ks=0) FIRST, then prefetch issue -> MMAs start early.
// EPI: 0 = bias -> half, 1 = bias + residual -> float, 2 = bias + relu -> half
// ---------------------------------------------------------------------------
#define STAGES 3
#define TSTRIDE 72                       // halfs per row (BK=64 + pad 8)
#define A_HALFS (256 * TSTRIDE)          // 18432 halfs
#define B_HALFS (128 * TSTRIDE)          // 9216 halfs
#define STG_HALFS (A_HALFS + B_HALFS)    // 27648 halfs
#define GEMM_SMEM (STAGES * STG_HALFS * 2)   // 165888 B

template <int EPI>
__global__ __launch_bounds__(256, 1)
void hgemm_kernel(const __half* __restrict__ A, const __half* __restrict__ B,
                  const float* __restrict__ bias, const float* __restrict__ Res,
                  void* __restrict__ Cout, int M, int N, int K) {
    extern __shared__ __half hsmem[];

    const int tid  = threadIdx.x;
    const int warp = tid >> 5;
    const int lane = tid & 31;
    const int gid  = lane >> 2;
    const int tig  = lane & 3;
    const int part = lane >> 3, pr = lane & 7;
    const int wm   = (warp >> 1) * 64;   // m offset (4 warp-rows)
    const int wn   = (warp & 1) * 64;    // n offset (2 warp-cols)
    const int m0   = blockIdx.y * 256;
    const int n0   = blockIdx.x * 128;
    const int NIT  = K >> 6;

    float acc[4][8][4];
    #pragma unroll
    for (int i = 0; i < 4; i++)
        #pragma unroll
        for (int j = 0; j < 8; j++)
            #pragma unroll
            for (int r = 0; r < 4; r++) acc[i][j][r] = 0.f;

    auto load_tile = [&](int it, int stage) {
        __half* dA = hsmem + stage * STG_HALFS;
        __half* dB = dA + A_HALFS;
        const int kbase = it * 64;
        #pragma unroll
        for (int s = 0; s < 8; s++) {
            const int seg = s * 256 + tid;        // 0..2047
            const int r  = seg >> 3;              // 0..255
            const int kk = (seg & 7) << 3;        // 0..56
            cp_async16(dA + r * TSTRIDE + kk, A + (size_t)(m0 + r) * K + kbase + kk);
        }
        #pragma unroll
        for (int s = 0; s < 4; s++) {
            const int seg = s * 256 + tid;        // 0..1023
            const int r  = seg >> 3;              // 0..127
            const int kk = (seg & 7) << 3;
            cp_async16(dB + r * TSTRIDE + kk, B + (size_t)(n0 + r) * K + kbase + kk);
        }
        asm volatile("cp.async.commit_group;");
    };

    load_tile(0, 0);
    load_tile(1, 1);

    const int arow = (part & 1) * 8 + pr;

    int st = 0, ldst = 2;
    for (int it = 0; it < NIT; it++) {
        asm volatile("cp.async.wait_group 1;");
        __syncthreads();

        const __half* hA = hsmem + st * STG_HALFS;
        const __half* hB = hA + A_HALFS;
        st = (st == 2) ? 0 : st + 1;

        uint32_t af[2][4][4], bf[2][4][4];

        auto ld_frags = [&](int ks, uint32_t a_[4][4], uint32_t b_[4][4]) {
            #pragma unroll
            for (int i = 0; i < 4; i++)
                ldsm4(a_[i], smem_u32(
                    &hA[(wm + 16 * i + arow) * TSTRIDE + 16 * ks + (part >> 1) * 8]));
            #pragma unroll
            for (int j2 = 0; j2 < 4; j2++)
                ldsm4(b_[j2], smem_u32(
                    &hB[(wn + 8 * (2 * j2 + (part >> 1)) + pr) * TSTRIDE + 16 * ks + (part & 1) * 8]));
        };

        // frags for ks=0 FIRST so MMAs can start before the cp.async burst
        ld_frags(0, af[0], bf[0]);

        if (it + 2 < NIT) {
            load_tile(it + 2, ldst);
            ldst = (ldst == 2) ? 0 : ldst + 1;
        }

        #pragma unroll
        for (int ks = 0; ks < 4; ks++) {
            const int cur = ks & 1;
            if (ks < 3) ld_frags(ks + 1, af[cur ^ 1], bf[cur ^ 1]);
            #pragma unroll
            for (int i = 0; i < 4; i++)
                #pragma unroll
                for (int j = 0; j < 8; j++)
                    mma_f16(acc[i][j], af[cur][i], bf[cur][j >> 1] + (j & 1) * 2);
        }
    }

    // epilogue
    #pragma unroll
    for (int i = 0; i < 4; i++) {
        #pragma unroll
        for (int half = 0; half < 2; half++) {
            const int r = m0 + wm + i * 16 + gid + half * 8;
            const size_t rowoff = (size_t)r * N;
            #pragma unroll
            for (int j = 0; j < 8; j++) {
                const int c = n0 + wn + j * 8 + tig * 2;
                float v0 = acc[i][j][half * 2 + 0] + bias[c];
                float v1 = acc[i][j][half * 2 + 1] + bias[c + 1];
                if (EPI == 1) {
                    float2 r2 = *(const float2*)(Res + rowoff + c);
                    v0 += r2.x; v1 += r2.y;
                    float2 o; o.x = v0; o.y = v1;
                    *(float2*)((float*)Cout + rowoff + c) = o;
                } else {
                    if (EPI == 2) { v0 = fmaxf(v0, 0.f); v1 = fmaxf(v1, 0.f); }
                    *(__half2*)((__half*)Cout + rowoff + c) = __floats2half2_rn(v0, v1);
                }
            }
        }
    }
}

// ---------------------------------------------------------------------------
// Tensor-core causal flash attention, q-tile 128, kv-tile 64, 256 threads.
// Longest-first scheduling: blockIdx.x=0 gets the LARGEST qb.
// ---------------------------------------------------------------------------
#define ASTR 72
#define SQ_H (128 * ASTR)          // 9216 halfs
#define SKV_H (64 * ASTR)          // 4608 halfs per buffer
#define ATTN_SMEM ((SQ_H + 4 * SKV_H) * 2)   // 55296 B

__global__ __launch_bounds__(256)
void attn_kernel(const __half* __restrict__ qkv, __half* __restrict__ y) {
    extern __shared__ __half as[];
    __half* sQ = as;                    // [128][72]
    __half* sK = as + SQ_H;             // [2][64][72]
    __half* sV = as + SQ_H + 2 * SKV_H; // [2][64][72]

    const int tid  = threadIdx.x;
    const int warp = tid >> 5, lane = tid & 31;
    const int gid  = lane >> 2, tig = lane & 3;
    const int part = lane >> 3, pr = lane & 7;
    const int qb = gridDim.x - 1 - blockIdx.x;   // longest-first
    const int h = blockIdx.y, b = blockIdx.z;
    const size_t base = (size_t)b * TT * (3 * CC) + (size_t)h * DD;

    #pragma unroll
    for (int i = 0; i < 4; i++) {
        const int seg = i * 256 + tid;
        const int r = seg >> 3, c8 = (seg & 7) << 3;
        cp_async16(&sQ[r * ASTR + c8], qkv + base + (size_t)(qb * 128 + r) * (3 * CC) + c8);
    }
    #pragma unroll
    for (int i = 0; i < 2; i++) {
        const int seg = i * 256 + tid;
        const int r = seg >> 3, c8 = (seg & 7) << 3;
        const size_t ka = base + CC + (size_t)r * (3 * CC) + c8;
        cp_async16(&sK[r * ASTR + c8], qkv + ka);
        cp_async16(&sV[r * ASTR + c8], qkv + ka + CC);
    }
    asm volatile("cp.async.commit_group;");

    float o[8][4];
    #pragma unroll
    for (int j = 0; j < 8; j++)
        #pragma unroll
        for (int r = 0; r < 4; r++) o[j][r] = 0.f;
    float m0 = -1e30f, m1 = -1e30f, l0 = 0.f, l1 = 0.f;
    uint32_t qf[4][4];

    const int arow0 = qb * 128 + 16 * warp + gid;
    const int wrow_max = qb * 128 + 16 * warp + 15;
    const int KBMAX = 2 * qb + 1;

    for (int kb = 0; kb <= KBMAX; kb++) {
        const int buf = kb & 1;
        if (kb < KBMAX) {
            #pragma unroll
            for (int i = 0; i < 2; i++) {
                const int seg = i * 256 + tid;
                const int r = seg >> 3, c8 = (seg & 7) << 3;
                const size_t ka = base + CC + (size_t)((kb + 1) * 64 + r) * (3 * CC) + c8;
                cp_async16(&sK[(buf ^ 1) * SKV_H + r * ASTR + c8], qkv + ka);
                cp_async16(&sV[(buf ^ 1) * SKV_H + r * ASTR + c8], qkv + ka + CC);
            }
            asm volatile("cp.async.commit_group;");
            asm volatile("cp.async.wait_group 1;");
        } else {
            asm volatile("cp.async.wait_group 0;");
        }
        __syncthreads();

        if (kb == 0) {
            #pragma unroll
            for (int ks = 0; ks < 4; ks++)
                ldsm4(qf[ks], smem_u32(
                    &sQ[(16 * warp + (part & 1) * 8 + pr) * ASTR + 16 * ks + (part >> 1) * 8]));
        }

        const bool skip = (64 * kb > wrow_max);
        if (!skip) {
            float s[8][4];
            #pragma unroll
            for (int j = 0; j < 8; j++)
                #pragma unroll
                for (int r = 0; r < 4; r++) s[j][r] = 0.f;

            #pragma unroll
            for (int ks = 0; ks < 4; ks++) {
                #pragma unroll
                for (int j2 = 0; j2 < 8; j2 += 2) {
                    uint32_t kf[4];
                    ldsm4(kf, smem_u32(
                        &sK[buf * SKV_H + (8 * (j2 + (part >> 1)) + pr) * ASTR + 16 * ks + (part & 1) * 8]));
                    mma_f16(s[j2],     qf[ks], kf);
                    mma_f16(s[j2 + 1], qf[ks], kf + 2);
                }
            }

            if (kb >= 2 * qb) {
                #pragma unroll
                for (int j = 0; j < 8; j++) {
                    const int c0 = 64 * kb + 8 * j + 2 * tig;
                    if (c0     > arow0)     s[j][0] = -1e30f;
                    if (c0 + 1 > arow0)     s[j][1] = -1e30f;
                    if (c0     > arow0 + 8) s[j][2] = -1e30f;
                    if (c0 + 1 > arow0 + 8) s[j][3] = -1e30f;
                }
            }

            float mx0 = -1e30f, mx1 = -1e30f;
            #pragma unroll
            for (int j = 0; j < 8; j++) {
                mx0 = fmaxf(mx0, fmaxf(s[j][0], s[j][1]));
                mx1 = fmaxf(mx1, fmaxf(s[j][2], s[j][3]));
            }
            mx0 = fmaxf(mx0, __shfl_xor_sync(0xffffffffu, mx0, 1));
            mx0 = fmaxf(mx0, __shfl_xor_sync(0xffffffffu, mx0, 2));
            mx1 = fmaxf(mx1, __shfl_xor_sync(0xffffffffu, mx1, 1));
            mx1 = fmaxf(mx1, __shfl_xor_sync(0xffffffffu, mx1, 2));

            const float mn0 = fmaxf(m0, mx0 * SCALE_ATTN);
            const float mn1 = fmaxf(m1, mx1 * SCALE_ATTN);
            const float cr0 = __expf(m0 - mn0), cr1 = __expf(m1 - mn1);
            m0 = mn0; m1 = mn1;

            float rs0 = 0.f, rs1 = 0.f;
            #pragma unroll
            for (int j = 0; j < 8; j++) {
                s[j][0] = __expf(fmaf(s[j][0], SCALE_ATTN, -mn0));
                s[j][1] = __expf(fmaf(s[j][1], SCALE_ATTN, -mn0));
                rs0 += s[j][0] + s[j][1];
                s[j][2] = __expf(fmaf(s[j][2], SCALE_ATTN, -mn1));
                s[j][3] = __expf(fmaf(s[j][3], SCALE_ATTN, -mn1));
                rs1 += s[j][2] + s[j][3];
            }
            rs0 += __shfl_xor_sync(0xffffffffu, rs0, 1);
            rs0 += __shfl_xor_sync(0xffffffffu, rs0, 2);
            rs1 += __shfl_xor_sync(0xffffffffu, rs1, 1);
            rs1 += __shfl_xor_sync(0xffffffffu, rs1, 2);
            l0 = l0 * cr0 + rs0;
            l1 = l1 * cr1 + rs1;
            #pragma unroll
            for (int j = 0; j < 8; j++) {
                o[j][0] *= cr0; o[j][1] *= cr0;
                o[j][2] *= cr1; o[j][3] *= cr1;
            }

            #pragma unroll
            for (int kk = 0; kk < 4; kk++) {
                uint32_t pa[4];
                pa[0] = h2bits(s[2 * kk][0],     s[2 * kk][1]);
                pa[1] = h2bits(s[2 * kk][2],     s[2 * kk][3]);
                pa[2] = h2bits(s[2 * kk + 1][0], s[2 * kk + 1][1]);
                pa[3] = h2bits(s[2 * kk + 1][2], s[2 * kk + 1][3]);
                #pragma unroll
                for (int jd = 0; jd < 8; jd += 2) {
                    uint32_t vf[4];
                    ldsm4t(vf, smem_u32(
                        &sV[buf * SKV_H + (16 * kk + (part & 1) * 8 + pr) * ASTR + 8 * (jd + (part >> 1))]));
                    mma_f16(o[jd],     pa, vf);
                    mma_f16(o[jd + 1], pa, vf + 2);
                }
            }
        }
        __syncthreads();
    }

    const float i0 = 1.f / l0, i1 = 1.f / l1;
    const int r0 = qb * 128 + 16 * warp + gid;
    #pragma unroll
    for (int j = 0; j < 8; j++) {
        const int col = h * DD + 8 * j + 2 * tig;
        *(__half2*)(y + (size_t)(b * TT + r0) * CC + col) =
            __floats2half2_rn(o[j][0] * i0, o[j][1] * i0);
        *(__half2*)(y + (size_t)(b * TT + r0 + 8) * CC + col) =
            __floats2half2_rn(o[j][2] * i1, o[j][3] * i1);
    }
}

// ---------------------------------------------------------------------------
// Launch — transposes overlapped on a side stream (fork-join, graph-capturable)
// ---------------------------------------------------------------------------
extern "C" void kernel_launch(void* const* d_in, const int* in_sizes, int n_in,
                              void* d_out, int out_size) {
    const float* x     = (const float*)d_in[0];
    const float* Wqkv  = (const float*)d_in[1];
    const float* bqkv  = (const float*)d_in[2];
    const float* Wproj = (const float*)d_in[3];
    const float* bproj = (const float*)d_in[4];
    const float* ln1_g = (const float*)d_in[5];
    const float* ln1_b = (const float*)d_in[6];
    const float* ln2_g = (const float*)d_in[7];
    const float* ln2_b = (const float*)d_in[8];
    const float* W1    = (const float*)d_in[9];
    const float* b1    = (const float*)d_in[10];
    const float* W2    = (const float*)d_in[11];
    const float* b2    = (const float*)d_in[12];
    float* out = (float*)d_out;

    __half *h, *qkv, *y, *h2, *mid, *wt;
    cudaGetSymbolAddress((void**)&h,   g_h);
    cudaGetSymbolAddress((void**)&qkv, g_qkv);
    cudaGetSymbolAddress((void**)&y,   g_y);
    cudaGetSymbolAddress((void**)&h2,  g_h2);
    cudaGetSymbolAddress((void**)&mid, g_mid);
    cudaGetSymbolAddress((void**)&wt,  g_wt);

    static cudaStream_t s_side = nullptr;
    static cudaEvent_t ev_fork = nullptr, ev_qkv = nullptr, ev_rest = nullptr;
    static int init_done = 0;
    if (!init_done) {
        cudaFuncSetAttribute(hgemm_kernel<0>, cudaFuncAttributeMaxDynamicSharedMemorySize, GEMM_SMEM);
        cudaFuncSetAttribute(hgemm_kernel<1>, cudaFuncAttributeMaxDynamicSharedMemorySize, GEMM_SMEM);
        cudaFuncSetAttribute(hgemm_kernel<2>, cudaFuncAttributeMaxDynamicSharedMemorySize, GEMM_SMEM);
        cudaFuncSetAttribute(attn_kernel, cudaFuncAttributeMaxDynamicSharedMemorySize, ATTN_SMEM);
        cudaStreamCreateWithFlags(&s_side, cudaStreamNonBlocking);
        cudaEventCreateWithFlags(&ev_fork, cudaEventDisableTiming);
        cudaEventCreateWithFlags(&ev_qkv,  cudaEventDisableTiming);
        cudaEventCreateWithFlags(&ev_rest, cudaEventDisableTiming);
        init_done = 1;
    }

    // fork: side stream does the 4 weight transposes
    cudaEventRecord(ev_fork, 0);
    cudaStreamWaitEvent(s_side, ev_fork, 0);
    transpose_w<<<dim3(3 * CC / 32, CC / 32), dim3(32, 8), 0, s_side>>>(Wqkv, wt + OFF_QKV, CC, 3 * CC);
    cudaEventRecord(ev_qkv, s_side);
    transpose_w<<<dim3(CC / 32, CC / 32),     dim3(32, 8), 0, s_side>>>(Wproj, wt + OFF_PROJ, CC, CC);
    transpose_w<<<dim3(4 * CC / 32, CC / 32), dim3(32, 8), 0, s_side>>>(W1,    wt + OFF_W1,   CC, 4 * CC);
    transpose_w<<<dim3(CC / 32, 4 * CC / 32), dim3(32, 8), 0, s_side>>>(W2,    wt + OFF_W2,   4 * CC, CC);
    cudaEventRecord(ev_rest, s_side);

    // main stream: ln1 overlaps with transposes
    ln_kernel<<<NTOK, 256>>>(x, ln1_g, ln1_b, h);
    cudaStreamWaitEvent(0, ev_qkv, 0);
    // 2. qkv = h @ Wqkv + bqkv   (half out)
    hgemm_kernel<0><<<dim3(3 * CC / 128, NTOK / 256), 256, GEMM_SMEM>>>(
        h, wt + OFF_QKV, bqkv, nullptr, qkv, NTOK, 3 * CC, CC);
    // 3. y = causal_attention(qkv)
    attn_kernel<<<dim3(TT / 128, HH, BB), 256, ATTN_SMEM>>>(qkv, y);
    cudaStreamWaitEvent(0, ev_rest, 0);
    // 4. out = x + y @ Wproj + bproj   (float out)
    hgemm_kernel<1><<<dim3(CC / 128, NTOK / 256), 256, GEMM_SMEM>>>(
        y, wt + OFF_PROJ, bproj, x, out, NTOK, CC, CC);
    // 5. h2 = ln2(out)
    ln_kernel<<<NTOK, 256>>>(out, ln2_g, ln2_b, h2);
    // 6. mid = relu(h2 @ W1 + b1)   (half out)
    hgemm_kernel<2><<<dim3(4 * CC / 128, NTOK / 256), 256, GEMM_SMEM>>>(
        h2, wt + OFF_W1, b1, nullptr, mid, NTOK, 4 * CC, CC);
    // 7. out = out + mid @ W2 + b2   (float out, K=4096)
    hgemm_kernel<1><<<dim3(CC / 128, NTOK / 256), 256, GEMM_SMEM>>>(
        mid, wt + OFF_W2, b2, out, out, NTOK, CC, 4 * CC);
}

// round 17
// speedup vs baseline: 1.0662x; 1.0662x over previous
#include <cuda_runtime.h>
#include <cuda_fp16.h>
#include <cstdint>

// ---------------------------------------------------------------------------
// Problem constants
// ---------------------------------------------------------------------------
#define BB 8
#define TT 1024
#define CC 1024
#define HH 16
#define DD 64
#define NTOK (BB * TT)           // 8192
#define SCALE_ATTN 0.07216878364870323f  // 1/sqrt(3*C/H) = 1/sqrt(192)

// ---------------------------------------------------------------------------
// Scratch (device globals) — fp16 activations
// ---------------------------------------------------------------------------
__device__ __half g_h[NTOK * CC];          // ln1 out
__device__ __half g_qkv[NTOK * 3 * CC];    // qkv
__device__ __half g_y[NTOK * CC];          // attn out
__device__ __half g_h2[NTOK * CC];         // ln2 out
__device__ __half g_mid[NTOK * 4 * CC];    // mlp hidden
// transposed fp16 weights, [N][K] row-major
#define OFF_QKV  0
#define OFF_PROJ (3 * CC * CC)
#define OFF_W1   (OFF_PROJ + CC * CC)
#define OFF_W2   (OFF_W1 + 4 * CC * CC)
#define WP_TOTAL (OFF_W2 + 4 * CC * CC)
__device__ __half g_wt[WP_TOTAL];

// ---------------------------------------------------------------------------
// Helpers
// ---------------------------------------------------------------------------
__device__ __forceinline__ void mma_f16(float* c, const uint32_t* a, const uint32_t* b) {
    asm volatile(
        "mma.sync.aligned.m16n8k16.row.col.f32.f16.f16.f32 "
        "{%0,%1,%2,%3}, {%4,%5,%6,%7}, {%8,%9}, {%0,%1,%2,%3};"
        : "+f"(c[0]), "+f"(c[1]), "+f"(c[2]), "+f"(c[3])
        : "r"(a[0]), "r"(a[1]), "r"(a[2]), "r"(a[3]), "r"(b[0]), "r"(b[1]));
}

__device__ __forceinline__ void cp_async16(void* smem_ptr, const void* gptr) {
    uint32_t sp = (uint32_t)__cvta_generic_to_shared(smem_ptr);
    asm volatile("cp.async.ca.shared.global [%0], [%1], 16;" :: "r"(sp), "l"(gptr));
}

__device__ __forceinline__ uint32_t smem_u32(const void* p) {
    return (uint32_t)__cvta_generic_to_shared(p);
}

__device__ __forceinline__ void ldsm4(uint32_t* r, uint32_t a) {
    asm volatile("ldmatrix.sync.aligned.m8n8.x4.shared.b16 {%0,%1,%2,%3}, [%4];"
        : "=r"(r[0]), "=r"(r[1]), "=r"(r[2]), "=r"(r[3]) : "r"(a));
}
__device__ __forceinline__ void ldsm4t(uint32_t* r, uint32_t a) {
    asm volatile("ldmatrix.sync.aligned.m8n8.x4.trans.shared.b16 {%0,%1,%2,%3}, [%4];"
        : "=r"(r[0]), "=r"(r[1]), "=r"(r[2]), "=r"(r[3]) : "r"(a));
}

__device__ __forceinline__ uint32_t h2bits(float a, float b) {
    __half2 h = __floats2half2_rn(a, b);
    return *reinterpret_cast<uint32_t*>(&h);
}

// ---------------------------------------------------------------------------
// Weight transpose + fp16 round: W[K][N] fp32 -> Wt[N][K] fp16
// ---------------------------------------------------------------------------
__global__ __launch_bounds__(256)
void transpose_w(const float* __restrict__ W, __half* __restrict__ Wt, int K, int N) {
    __shared__ float t[32][33];
    const int n0 = blockIdx.x * 32;
    const int k0 = blockIdx.y * 32;
    const int tx = threadIdx.x, ty = threadIdx.y;
    #pragma unroll
    for (int i = 0; i < 4; i++)
        t[ty + 8 * i][tx] = W[(size_t)(k0 + ty + 8 * i) * N + n0 + tx];
    __syncthreads();
    #pragma unroll
    for (int i = 0; i < 4; i++)
        Wt[(size_t)(n0 + ty + 8 * i) * K + k0 + tx] = __float2half_rn(t[tx][ty + 8 * i]);
}

// ---------------------------------------------------------------------------
// LayerNorm: one block per row; fp32 in -> fp16 out
// ---------------------------------------------------------------------------
__global__ __launch_bounds__(256)
void ln_kernel(const float* __restrict__ x, const float* __restrict__ g,
               const float* __restrict__ b, __half* __restrict__ out) {
    __shared__ float rs[8];
    __shared__ float rq[8];
    const int row = blockIdx.x;
    const float* xr = x + (size_t)row * CC;
    __half* yr = out + (size_t)row * CC;
    const int c = threadIdx.x * 4;

    float4 v = *(const float4*)(xr + c);
    float s  = v.x + v.y + v.z + v.w;
    float sq = v.x * v.x + v.y * v.y + v.z * v.z + v.w * v.w;
    #pragma unroll
    for (int o = 16; o; o >>= 1) {
        s  += __shfl_xor_sync(0xffffffffu, s, o);
        sq += __shfl_xor_sync(0xffffffffu, sq, o);
    }
    if ((threadIdx.x & 31) == 0) { rs[threadIdx.x >> 5] = s; rq[threadIdx.x >> 5] = sq; }
    __syncthreads();
    s = 0.f; sq = 0.f;
    #pragma unroll
    for (int i = 0; i < 8; i++) { s += rs[i]; sq += rq[i]; }

    const float mean = s * (1.f / CC);
    const float var  = sq * (1.f / CC) - mean * mean;
    const float rstd = rsqrtf(var + 1e-5f);

    float4 g4 = *(const float4*)(g + c);
    float4 b4 = *(const float4*)(b + c);
    *(__half2*)(yr + c)     = __floats2half2_rn((v.x - mean) * rstd * g4.x + b4.x,
                                                (v.y - mean) * rstd * g4.y + b4.y);
    *(__half2*)(yr + c + 2) = __floats2half2_rn((v.z - mean) * rstd * g4.z + b4.z,
                                                (v.w - mean) * rstd * g4.w + b4.w);
}

// ---------------------------------------------------------------------------
// FP16 tensor GEMM (R11 config — do not touch):
// CTA tile 256x128, BK=64, 3-stage cp.async (.ca), one sync per k-iter,
// 8 warps (4m x 2n), warp tile 64x64, register double-buffered ldmatrix feed.
// EPI: 0 = bias -> half, 1 = bias + residual -> float, 2 = bias + relu -> half
// ---------------------------------------------------------------------------
#define STAGES 3
#define TSTRIDE 72                       // halfs per row (BK=64 + pad 8)
#define A_HALFS (256 * TSTRIDE)          // 18432 halfs
#define B_HALFS (128 * TSTRIDE)          // 9216 halfs
#define STG_HALFS (A_HALFS + B_HALFS)    // 27648 halfs
#define GEMM_SMEM (STAGES * STG_HALFS * 2)   // 165888 B

template <int EPI>
__global__ __launch_bounds__(256, 1)
void hgemm_kernel(const __half* __restrict__ A, const __half* __restrict__ B,
                  const float* __restrict__ bias, const float* __restrict__ Res,
                  void* __restrict__ Cout, int M, int N, int K) {
    extern __shared__ __half hsmem[];

    const int tid  = threadIdx.x;
    const int warp = tid >> 5;
    const int lane = tid & 31;
    const int gid  = lane >> 2;
    const int tig  = lane & 3;
    const int part = lane >> 3, pr = lane & 7;
    const int wm   = (warp >> 1) * 64;   // m offset (4 warp-rows)
    const int wn   = (warp & 1) * 64;    // n offset (2 warp-cols)
    const int m0   = blockIdx.y * 256;
    const int n0   = blockIdx.x * 128;
    const int NIT  = K >> 6;

    float acc[4][8][4];
    #pragma unroll
    for (int i = 0; i < 4; i++)
        #pragma unroll
        for (int j = 0; j < 8; j++)
            #pragma unroll
            for (int r = 0; r < 4; r++) acc[i][j][r] = 0.f;

    auto load_tile = [&](int it, int stage) {
        __half* dA = hsmem + stage * STG_HALFS;
        __half* dB = dA + A_HALFS;
        const int kbase = it * 64;
        #pragma unroll
        for (int s = 0; s < 8; s++) {
            const int seg = s * 256 + tid;        // 0..2047
            const int r  = seg >> 3;              // 0..255
            const int kk = (seg & 7) << 3;        // 0..56
            cp_async16(dA + r * TSTRIDE + kk, A + (size_t)(m0 + r) * K + kbase + kk);
        }
        #pragma unroll
        for (int s = 0; s < 4; s++) {
            const int seg = s * 256 + tid;        // 0..1023
            const int r  = seg >> 3;              // 0..127
            const int kk = (seg & 7) << 3;
            cp_async16(dB + r * TSTRIDE + kk, B + (size_t)(n0 + r) * K + kbase + kk);
        }
        asm volatile("cp.async.commit_group;");
    };

    load_tile(0, 0);
    load_tile(1, 1);

    const int arow = (part & 1) * 8 + pr;

    int st = 0, ldst = 2;
    for (int it = 0; it < NIT; it++) {
        asm volatile("cp.async.wait_group 1;");
        __syncthreads();

        if (it + 2 < NIT) {
            load_tile(it + 2, ldst);
            ldst = (ldst == 2) ? 0 : ldst + 1;
        }

        const __half* hA = hsmem + st * STG_HALFS;
        const __half* hB = hA + A_HALFS;
        st = (st == 2) ? 0 : st + 1;

        uint32_t af[2][4][4], bf[2][4][4];

        auto ld_frags = [&](int ks, uint32_t a_[4][4], uint32_t b_[4][4]) {
            #pragma unroll
            for (int i = 0; i < 4; i++)
                ldsm4(a_[i], smem_u32(
                    &hA[(wm + 16 * i + arow) * TSTRIDE + 16 * ks + (part >> 1) * 8]));
            #pragma unroll
            for (int j2 = 0; j2 < 4; j2++)
                ldsm4(b_[j2], smem_u32(
                    &hB[(wn + 8 * (2 * j2 + (part >> 1)) + pr) * TSTRIDE + 16 * ks + (part & 1) * 8]));
        };

        ld_frags(0, af[0], bf[0]);
        #pragma unroll
        for (int ks = 0; ks < 4; ks++) {
            const int cur = ks & 1;
            if (ks < 3) ld_frags(ks + 1, af[cur ^ 1], bf[cur ^ 1]);
            #pragma unroll
            for (int i = 0; i < 4; i++)
                #pragma unroll
                for (int j = 0; j < 8; j++)
                    mma_f16(acc[i][j], af[cur][i], bf[cur][j >> 1] + (j & 1) * 2);
        }
    }

    // epilogue
    #pragma unroll
    for (int i = 0; i < 4; i++) {
        #pragma unroll
        for (int half = 0; half < 2; half++) {
            const int r = m0 + wm + i * 16 + gid + half * 8;
            const size_t rowoff = (size_t)r * N;
            #pragma unroll
            for (int j = 0; j < 8; j++) {
                const int c = n0 + wn + j * 8 + tig * 2;
                float v0 = acc[i][j][half * 2 + 0] + bias[c];
                float v1 = acc[i][j][half * 2 + 1] + bias[c + 1];
                if (EPI == 1) {
                    float2 r2 = *(const float2*)(Res + rowoff + c);
                    v0 += r2.x; v1 += r2.y;
                    float2 o; o.x = v0; o.y = v1;
                    *(float2*)((float*)Cout + rowoff + c) = o;
                } else {
                    if (EPI == 2) { v0 = fmaxf(v0, 0.f); v1 = fmaxf(v1, 0.f); }
                    *(__half2*)((__half*)Cout + rowoff + c) = __floats2half2_rn(v0, v1);
                }
            }
        }
    }
}

// ---------------------------------------------------------------------------
// Tensor-core causal flash attention, q-tile 128, kv-tile 64, 256 threads.
// b0 = batch offset (for chunked launches); longest-first within chunk.
// ---------------------------------------------------------------------------
#define ASTR 72
#define SQ_H (128 * ASTR)          // 9216 halfs
#define SKV_H (64 * ASTR)          // 4608 halfs per buffer
#define ATTN_SMEM ((SQ_H + 4 * SKV_H) * 2)   // 55296 B

__global__ __launch_bounds__(256)
void attn_kernel(const __half* __restrict__ qkv, __half* __restrict__ y, int b0) {
    extern __shared__ __half as[];
    __half* sQ = as;                    // [128][72]
    __half* sK = as + SQ_H;             // [2][64][72]
    __half* sV = as + SQ_H + 2 * SKV_H; // [2][64][72]

    const int tid  = threadIdx.x;
    const int warp = tid >> 5, lane = tid & 31;
    const int gid  = lane >> 2, tig = lane & 3;
    const int part = lane >> 3, pr = lane & 7;
    const int qb = gridDim.x - 1 - blockIdx.x;   // longest-first
    const int h = blockIdx.y, b = blockIdx.z + b0;
    const size_t base = (size_t)b * TT * (3 * CC) + (size_t)h * DD;

    #pragma unroll
    for (int i = 0; i < 4; i++) {
        const int seg = i * 256 + tid;
        const int r = seg >> 3, c8 = (seg & 7) << 3;
        cp_async16(&sQ[r * ASTR + c8], qkv + base + (size_t)(qb * 128 + r) * (3 * CC) + c8);
    }
    #pragma unroll
    for (int i = 0; i < 2; i++) {
        const int seg = i * 256 + tid;
        const int r = seg >> 3, c8 = (seg & 7) << 3;
        const size_t ka = base + CC + (size_t)r * (3 * CC) + c8;
        cp_async16(&sK[r * ASTR + c8], qkv + ka);
        cp_async16(&sV[r * ASTR + c8], qkv + ka + CC);
    }
    asm volatile("cp.async.commit_group;");

    float o[8][4];
    #pragma unroll
    for (int j = 0; j < 8; j++)
        #pragma unroll
        for (int r = 0; r < 4; r++) o[j][r] = 0.f;
    float m0 = -1e30f, m1 = -1e30f, l0 = 0.f, l1 = 0.f;
    uint32_t qf[4][4];

    const int arow0 = qb * 128 + 16 * warp + gid;
    const int wrow_max = qb * 128 + 16 * warp + 15;
    const int KBMAX = 2 * qb + 1;

    for (int kb = 0; kb <= KBMAX; kb++) {
        const int buf = kb & 1;
        if (kb < KBMAX) {
            #pragma unroll
            for (int i = 0; i < 2; i++) {
                const int seg = i * 256 + tid;
                const int r = seg >> 3, c8 = (seg & 7) << 3;
                const size_t ka = base + CC + (size_t)((kb + 1) * 64 + r) * (3 * CC) + c8;
                cp_async16(&sK[(buf ^ 1) * SKV_H + r * ASTR + c8], qkv + ka);
                cp_async16(&sV[(buf ^ 1) * SKV_H + r * ASTR + c8], qkv + ka + CC);
            }
            asm volatile("cp.async.commit_group;");
            asm volatile("cp.async.wait_group 1;");
        } else {
            asm volatile("cp.async.wait_group 0;");
        }
        __syncthreads();

        if (kb == 0) {
            #pragma unroll
            for (int ks = 0; ks < 4; ks++)
                ldsm4(qf[ks], smem_u32(
                    &sQ[(16 * warp + (part & 1) * 8 + pr) * ASTR + 16 * ks + (part >> 1) * 8]));
        }

        const bool skip = (64 * kb > wrow_max);
        if (!skip) {
            float s[8][4];
            #pragma unroll
            for (int j = 0; j < 8; j++)
                #pragma unroll
                for (int r = 0; r < 4; r++) s[j][r] = 0.f;

            #pragma unroll
            for (int ks = 0; ks < 4; ks++) {
                #pragma unroll
                for (int j2 = 0; j2 < 8; j2 += 2) {
                    uint32_t kf[4];
                    ldsm4(kf, smem_u32(
                        &sK[buf * SKV_H + (8 * (j2 + (part >> 1)) + pr) * ASTR + 16 * ks + (part & 1) * 8]));
                    mma_f16(s[j2],     qf[ks], kf);
                    mma_f16(s[j2 + 1], qf[ks], kf + 2);
                }
            }

            if (kb >= 2 * qb) {
                #pragma unroll
                for (int j = 0; j < 8; j++) {
                    const int c0 = 64 * kb + 8 * j + 2 * tig;
                    if (c0     > arow0)     s[j][0] = -1e30f;
                    if (c0 + 1 > arow0)     s[j][1] = -1e30f;
                    if (c0     > arow0 + 8) s[j][2] = -1e30f;
                    if (c0 + 1 > arow0 + 8) s[j][3] = -1e30f;
                }
            }

            float mx0 = -1e30f, mx1 = -1e30f;
            #pragma unroll
            for (int j = 0; j < 8; j++) {
                mx0 = fmaxf(mx0, fmaxf(s[j][0], s[j][1]));
                mx1 = fmaxf(mx1, fmaxf(s[j][2], s[j][3]));
            }
            mx0 = fmaxf(mx0, __shfl_xor_sync(0xffffffffu, mx0, 1));
            mx0 = fmaxf(mx0, __shfl_xor_sync(0xffffffffu, mx0, 2));
            mx1 = fmaxf(mx1, __shfl_xor_sync(0xffffffffu, mx1, 1));
            mx1 = fmaxf(mx1, __shfl_xor_sync(0xffffffffu, mx1, 2));

            const float mn0 = fmaxf(m0, mx0 * SCALE_ATTN);
            const float mn1 = fmaxf(m1, mx1 * SCALE_ATTN);
            const float cr0 = __expf(m0 - mn0), cr1 = __expf(m1 - mn1);
            m0 = mn0; m1 = mn1;

            float rs0 = 0.f, rs1 = 0.f;
            #pragma unroll
            for (int j = 0; j < 8; j++) {
                s[j][0] = __expf(fmaf(s[j][0], SCALE_ATTN, -mn0));
                s[j][1] = __expf(fmaf(s[j][1], SCALE_ATTN, -mn0));
                rs0 += s[j][0] + s[j][1];
                s[j][2] = __expf(fmaf(s[j][2], SCALE_ATTN, -mn1));
                s[j][3] = __expf(fmaf(s[j][3], SCALE_ATTN, -mn1));
                rs1 += s[j][2] + s[j][3];
            }
            rs0 += __shfl_xor_sync(0xffffffffu, rs0, 1);
            rs0 += __shfl_xor_sync(0xffffffffu, rs0, 2);
            rs1 += __shfl_xor_sync(0xffffffffu, rs1, 1);
            rs1 += __shfl_xor_sync(0xffffffffu, rs1, 2);
            l0 = l0 * cr0 + rs0;
            l1 = l1 * cr1 + rs1;
            #pragma unroll
            for (int j = 0; j < 8; j++) {
                o[j][0] *= cr0; o[j][1] *= cr0;
                o[j][2] *= cr1; o[j][3] *= cr1;
            }

            #pragma unroll
            for (int kk = 0; kk < 4; kk++) {
                uint32_t pa[4];
                pa[0] = h2bits(s[2 * kk][0],     s[2 * kk][1]);
                pa[1] = h2bits(s[2 * kk][2],     s[2 * kk][3]);
                pa[2] = h2bits(s[2 * kk + 1][0], s[2 * kk + 1][1]);
                pa[3] = h2bits(s[2 * kk + 1][2], s[2 * kk + 1][3]);
                #pragma unroll
                for (int jd = 0; jd < 8; jd += 2) {
                    uint32_t vf[4];
                    ldsm4t(vf, smem_u32(
                        &sV[buf * SKV_H + (16 * kk + (part & 1) * 8 + pr) * ASTR + 8 * (jd + (part >> 1))]));
                    mma_f16(o[jd],     pa, vf);
                    mma_f16(o[jd + 1], pa, vf + 2);
                }
            }
        }
        __syncthreads();
    }

    const float i0 = 1.f / l0, i1 = 1.f / l1;
    const int r0 = qb * 128 + 16 * warp + gid;
    #pragma unroll
    for (int j = 0; j < 8; j++) {
        const int col = h * DD + 8 * j + 2 * tig;
        *(__half2*)(y + (size_t)(b * TT + r0) * CC + col) =
            __floats2half2_rn(o[j][0] * i0, o[j][1] * i0);
        *(__half2*)(y + (size_t)(b * TT + r0 + 8) * CC + col) =
            __floats2half2_rn(o[j][2] * i1, o[j][3] * i1);
    }
}

// ---------------------------------------------------------------------------
// Launch — side stream: transposes + attention chunk 0 (overlaps qkv chunk 1)
// ---------------------------------------------------------------------------
extern "C" void kernel_launch(void* const* d_in, const int* in_sizes, int n_in,
                              void* d_out, int out_size) {
    const float* x     = (const float*)d_in[0];
    const float* Wqkv  = (const float*)d_in[1];
    const float* bqkv  = (const float*)d_in[2];
    const float* Wproj = (const float*)d_in[3];
    const float* bproj = (const float*)d_in[4];
    const float* ln1_g = (const float*)d_in[5];
    const float* ln1_b = (const float*)d_in[6];
    const float* ln2_g = (const float*)d_in[7];
    const float* ln2_b = (const float*)d_in[8];
    const float* W1    = (const float*)d_in[9];
    const float* b1    = (const float*)d_in[10];
    const float* W2    = (const float*)d_in[11];
    const float* b2    = (const float*)d_in[12];
    float* out = (float*)d_out;

    __half *h, *qkv, *y, *h2, *mid, *wt;
    cudaGetSymbolAddress((void**)&h,   g_h);
    cudaGetSymbolAddress((void**)&qkv, g_qkv);
    cudaGetSymbolAddress((void**)&y,   g_y);
    cudaGetSymbolAddress((void**)&h2,  g_h2);
    cudaGetSymbolAddress((void**)&mid, g_mid);
    cudaGetSymbolAddress((void**)&wt,  g_wt);

    static cudaStream_t s_side = nullptr;
    static cudaEvent_t ev_fork = nullptr, ev_qkv = nullptr, ev_rest = nullptr;
    static cudaEvent_t ev_c0 = nullptr, ev_a0 = nullptr;
    static int init_done = 0;
    if (!init_done) {
        cudaFuncSetAttribute(hgemm_kernel<0>, cudaFuncAttributeMaxDynamicSharedMemorySize, GEMM_SMEM);
        cudaFuncSetAttribute(hgemm_kernel<1>, cudaFuncAttributeMaxDynamicSharedMemorySize, GEMM_SMEM);
        cudaFuncSetAttribute(hgemm_kernel<2>, cudaFuncAttributeMaxDynamicSharedMemorySize, GEMM_SMEM);
        cudaFuncSetAttribute(attn_kernel, cudaFuncAttributeMaxDynamicSharedMemorySize, ATTN_SMEM);
        cudaStreamCreateWithFlags(&s_side, cudaStreamNonBlocking);
        cudaEventCreateWithFlags(&ev_fork, cudaEventDisableTiming);
        cudaEventCreateWithFlags(&ev_qkv,  cudaEventDisableTiming);
        cudaEventCreateWithFlags(&ev_rest, cudaEventDisableTiming);
        cudaEventCreateWithFlags(&ev_c0,   cudaEventDisableTiming);
        cudaEventCreateWithFlags(&ev_a0,   cudaEventDisableTiming);
        init_done = 1;
    }

    const int HALF_M = NTOK / 2;   // 4096 tokens per chunk

    // fork: side stream does the 4 weight transposes
    cudaEventRecord(ev_fork, 0);
    cudaStreamWaitEvent(s_side, ev_fork, 0);
    transpose_w<<<dim3(3 * CC / 32, CC / 32), dim3(32, 8), 0, s_side>>>(Wqkv, wt + OFF_QKV, CC, 3 * CC);
    cudaEventRecord(ev_qkv, s_side);
    transpose_w<<<dim3(CC / 32, CC / 32),     dim3(32, 8), 0, s_side>>>(Wproj, wt + OFF_PROJ, CC, CC);
    transpose_w<<<dim3(4 * CC / 32, CC / 32), dim3(32, 8), 0, s_side>>>(W1,    wt + OFF_W1,   CC, 4 * CC);
    transpose_w<<<dim3(CC / 32, 4 * CC / 32), dim3(32, 8), 0, s_side>>>(W2,    wt + OFF_W2,   4 * CC, CC);
    cudaEventRecord(ev_rest, s_side);

    // main: ln1 overlaps with transposes
    ln_kernel<<<NTOK, 256>>>(x, ln1_g, ln1_b, h);
    cudaStreamWaitEvent(0, ev_qkv, 0);

    // 2a. qkv chunk 0 (batches 0-3)
    hgemm_kernel<0><<<dim3(3 * CC / 128, HALF_M / 256), 256, GEMM_SMEM>>>(
        h, wt + OFF_QKV, bqkv, nullptr, qkv, HALF_M, 3 * CC, CC);
    cudaEventRecord(ev_c0, 0);

    // 2b. qkv chunk 1 (batches 4-7)
    hgemm_kernel<0><<<dim3(3 * CC / 128, HALF_M / 256), 256, GEMM_SMEM>>>(
        h + (size_t)HALF_M * CC, wt + OFF_QKV, bqkv, nullptr,
        qkv + (size_t)HALF_M * 3 * CC, HALF_M, 3 * CC, CC);

    // 3a. attention chunk 0 on side stream (overlaps qkv chunk 1)
    cudaStreamWaitEvent(s_side, ev_c0, 0);
    attn_kernel<<<dim3(TT / 128, HH, BB / 2), 256, ATTN_SMEM, s_side>>>(qkv, y, 0);
    cudaEventRecord(ev_a0, s_side);

    // 3b. attention chunk 1 on main
    attn_kernel<<<dim3(TT / 128, HH, BB / 2), 256, ATTN_SMEM>>>(qkv, y, BB / 2);

    // join: proj needs all of y + Wproj transpose
    cudaStreamWaitEvent(0, ev_a0, 0);
    cudaStreamWaitEvent(0, ev_rest, 0);
    // 4. out = x + y @ Wproj + bproj   (float out)
    hgemm_kernel<1><<<dim3(CC / 128, NTOK / 256), 256, GEMM_SMEM>>>(
        y, wt + OFF_PROJ, bproj, x, out, NTOK, CC, CC);
    // 5. h2 = ln2(out)
    ln_kernel<<<NTOK, 256>>>(out, ln2_g, ln2_b, h2);
    // 6. mid = relu(h2 @ W1 + b1)   (half out)
    hgemm_kernel<2><<<dim3(4 * CC / 128, NTOK / 256), 256, GEMM_SMEM>>>(
        h2, wt + OFF_W1, b1, nullptr, mid, NTOK, 4 * CC, CC);
    // 7. out = out + mid @ W2 + b2   (float out, K=4096)
    hgemm_kernel<1><<<dim3(CC / 128, NTOK / 256), 256, GEMM_SMEM>>>(
        mid, wt + OFF_W2, b2, out, out, NTOK, CC, 4 * CC);
}